// round 5
// baseline (speedup 1.0000x reference)
#include <cuda_runtime.h>

// Problem constants
#define NPOL   2
#define NANT   64
#define NBL    2016
#define NTIMES 64
#define NFREQS 256

#define TF   (NTIMES * NFREQS)   // 16384
#define TF4  (TF / 4)            // 4096 float4 per (baseline|antenna) pol-component plane
#define V4S  (NBL * TF4)         // 8,257,536 : pol-component stride of V (float4 units)
#define J4S  (NANT * TF4)        // 262,144   : pol-component stride of jones (float4 units)

// 2 items per thread: block of 256 threads covers 512 consecutive float4 of one
// baseline plane (thread t handles base+t and base+t+256). 8 blocks per plane.
#define NTHREADS 256
#define NBLOCKS  (NBL * 8)       // 16128

__device__ __forceinline__ float4 f4_mul(float4 a, float4 b) {
    return make_float4(a.x * b.x, a.y * b.y, a.z * b.z, a.w * b.w);
}
__device__ __forceinline__ float4 f4_fma(float4 a, float4 b, float4 c) {
    return make_float4(fmaf(a.x, b.x, c.x), fmaf(a.y, b.y, c.y),
                       fmaf(a.z, b.z, c.z), fmaf(a.w, b.w, c.w));
}

// One 2x2 congruence on a float4 lane-bundle; reads V/jones at offset r, writes out.
__device__ __forceinline__ void jones_point(const float4* __restrict__ V,
                                            const float4* __restrict__ J,
                                            float4* __restrict__ out,
                                            int vb, int jb1, int jb2)
{
    float4 v00 = __ldcs(&V[vb]);
    float4 v01 = __ldcs(&V[vb + V4S]);
    float4 v10 = __ldcs(&V[vb + 2 * V4S]);
    float4 v11 = __ldcs(&V[vb + 3 * V4S]);

    float4 j1_00 = __ldg(&J[jb1]);
    float4 j1_01 = __ldg(&J[jb1 + J4S]);
    float4 j1_10 = __ldg(&J[jb1 + 2 * J4S]);
    float4 j1_11 = __ldg(&J[jb1 + 3 * J4S]);

    float4 j2_00 = __ldg(&J[jb2]);
    float4 j2_01 = __ldg(&J[jb2 + J4S]);
    float4 j2_10 = __ldg(&J[jb2 + 2 * J4S]);
    float4 j2_11 = __ldg(&J[jb2 + 3 * J4S]);

    float4 t00 = f4_fma(j1_00, v00, f4_mul(j1_01, v10));
    float4 t01 = f4_fma(j1_00, v01, f4_mul(j1_01, v11));
    float4 t10 = f4_fma(j1_10, v00, f4_mul(j1_11, v10));
    float4 t11 = f4_fma(j1_10, v01, f4_mul(j1_11, v11));

    float4 o00 = f4_fma(t00, j2_00, f4_mul(t01, j2_01));
    float4 o01 = f4_fma(t00, j2_10, f4_mul(t01, j2_11));
    float4 o10 = f4_fma(t10, j2_00, f4_mul(t11, j2_01));
    float4 o11 = f4_fma(t10, j2_10, f4_mul(t11, j2_11));

    __stcs(&out[vb],           o00);
    __stcs(&out[vb + V4S],     o01);
    __stcs(&out[vb + 2 * V4S], o10);
    __stcs(&out[vb + 3 * V4S], o11);
}

__global__ __launch_bounds__(NTHREADS, 3)
void jones_apply_kernel(const float4* __restrict__ V,     // (2,2,NBL,T,F) as float4
                        const float4* __restrict__ J,     // (2,2,NANT,T,F) as float4
                        const int*    __restrict__ ant1,
                        const int*    __restrict__ ant2,
                        float4*       __restrict__ out)   // (2,2,NBL,T,F) as float4
{
    int blk = blockIdx.x;
    int n   = blk >> 3;                       // baseline
    int r0  = ((blk & 7) << 9) + threadIdx.x; // base position in plane (float4 units)
    int r1  = r0 + 256;

    int a1 = __ldg(&ant1[n]);
    int a2 = __ldg(&ant2[n]);

    int nb  = n  * TF4;
    int j1b = a1 * TF4;
    int j2b = a2 * TF4;

    // Two independent work items: their 8 V-miss loads can all be in flight
    // together (deeper per-warp DRAM MLP than one-item-per-thread).
    jones_point(V, J, out, nb + r0, j1b + r0, j2b + r0);
    jones_point(V, J, out, nb + r1, j1b + r1, j2b + r1);
}

extern "C" void kernel_launch(void* const* d_in, const int* in_sizes, int n_in,
                              void* d_out, int out_size) {
    const float4* V    = (const float4*)d_in[0];   // V_m  float32 (2,2,2016,64,256)
    const float4* J    = (const float4*)d_in[1];   // jones float32 (2,2,64,64,256)
    const int*    ant1 = (const int*)d_in[2];
    const int*    ant2 = (const int*)d_in[3];
    float4*       out  = (float4*)d_out;

    jones_apply_kernel<<<NBLOCKS, NTHREADS>>>(V, J, ant1, ant2, out);
}